// round 10
// baseline (speedup 1.0000x reference)
#include <cuda_runtime.h>
#include <cuda_fp16.h>
#include <math.h>

#define PI_F 3.14159274101257324f   // float32(pi)
#define H 512
#define W 512
#define NIMG 32                      // 16 pred + 16 tgt
#define NBINS 24                     // 3 radial * 8 angle
#define KCOLS 257                    // Hermitian: only cols 0..256 stored

// ---- scratch (static device globals; no allocations allowed) ----
__device__ __half2 d_scratch[(size_t)NIMG * KCOLS * H];  // [img][kcol][row], 16.8 MB
struct Acc {
    float sums[NIMG * NBINS];
    int   counts[NBINS];
};
__device__ Acc d_acc;
__device__ __align__(16) uchar2 d_binpair[KCOLS * H];    // per (kcol,row): encoded bin + mirror bin

// float32 linspace(-1, 1, 512) as numpy/jax computes it: i*step + start
__device__ __forceinline__ float lin512(int i) {
    const float step = 2.0f / 511.0f;
    return (float)i * step + (-1.0f);
}
// fast hann window (MUFU cos; abs err ~5e-7, multiplied into input -> negligible)
__device__ __forceinline__ float hann512(int n) {
    return 0.5f * (1.0f - __cosf((6.283185307179586f * (float)n) / 511.0f));
}

// ---------------- packed f32x2 helpers ----------------
__device__ __forceinline__ float2 f2add(float2 a, float2 b) {
    unsigned long long au = *(unsigned long long*)&a;
    unsigned long long bu = *(unsigned long long*)&b;
    unsigned long long ru;
    asm("add.rn.f32x2 %0, %1, %2;" : "=l"(ru) : "l"(au), "l"(bu));
    return *(float2*)&ru;
}
__device__ __forceinline__ float2 f2sub(float2 a, float2 b) {
    unsigned long long au = *(unsigned long long*)&a;
    unsigned long long bu = *(unsigned long long*)&b;
    const float2 n1 = make_float2(-1.0f, -1.0f);
    unsigned long long nu = *(unsigned long long*)&n1;
    unsigned long long ru;
    asm("fma.rn.f32x2 %0, %1, %2, %3;" : "=l"(ru) : "l"(bu), "l"(nu), "l"(au));
    return *(float2*)&ru;
}
__device__ __forceinline__ float2 f2mul(float2 a, float2 b) {
    unsigned long long au = *(unsigned long long*)&a;
    unsigned long long bu = *(unsigned long long*)&b;
    unsigned long long ru;
    asm("mul.rn.f32x2 %0, %1, %2;" : "=l"(ru) : "l"(au), "l"(bu));
    return *(float2*)&ru;
}

// ---------------- complex helpers ----------------
__device__ __forceinline__ float2 cmul(float2 a, float2 b){return make_float2(a.x*b.x-a.y*b.y, a.x*b.y+a.y*b.x);}
__device__ __forceinline__ float2 mulmj(float2 a){return make_float2(a.y,-a.x);} // * (-i)

// 8-point DFT in registers (DIF, natural frequency order out)
__device__ __forceinline__ void fft8(float2 r[8]) {
    const float Cc = 0.70710678118654752f;
    const float2 C2 = make_float2(Cc, Cc);
    float2 u0=f2add(r[0],r[4]), u4=f2sub(r[0],r[4]);
    float2 u1=f2add(r[1],r[5]), u5=f2sub(r[1],r[5]);
    float2 u2=f2add(r[2],r[6]), u6=f2sub(r[2],r[6]);
    float2 u3=f2add(r[3],r[7]), u7=f2sub(r[3],r[7]);
    float2 t5 = f2add(u5, mulmj(u5));      // (x+y, y-x)
    u5 = f2mul(t5, C2);                    // * W8^1
    u6 = mulmj(u6);                        // * W8^2
    float2 t7 = f2add(u7, mulmj(u7));
    u7 = f2mul(mulmj(t7), C2);             // * W8^3
    float2 v0=f2add(u0,u2), v2=f2sub(u0,u2);
    float2 v1=f2add(u1,u3), v3=mulmj(f2sub(u1,u3));
    float2 v4=f2add(u4,u6), v6=f2sub(u4,u6);
    float2 v5=f2add(u5,u7), v7=mulmj(f2sub(u5,u7));
    r[0]=f2add(v0,v1); r[4]=f2sub(v0,v1);
    r[2]=f2add(v2,v3); r[6]=f2sub(v2,v3);
    r[1]=f2add(v4,v5); r[5]=f2sub(v4,v5);
    r[3]=f2add(v6,v7); r[7]=f2sub(v6,v7);
}

#define PADF 72    // float2 stride: 72 mod 16 == 8 -> conflict-free LDS.64/STS.64 both exchanges
#define SLOT 576   // float2 per slot (max idx 574)

// natural-order padded index (conflict-free for consecutive-row reads)
__device__ __forceinline__ int natidx(int k){ return 9*(k>>3) + (k&7); }

// 512-pt FFT: 64 threads (tl), 8 values/thread. Input r[j] = x[tl + 64*j].
// Output: r[k2] = X[k0 + 8*k1 + 64*k2] with k0 = tl>>3, k1 = tl&7.
__device__ __forceinline__ void fft512(float2 r[8], float2* sh, int tl) {
    fft8(r);
    float s, c;
    __sincosf(-6.283185307179586f * (float)tl / 512.0f, &s, &c);
    float2 w = make_float2(c, s), wk = w;
    #pragma unroll
    for (int k = 1; k < 8; k++) { r[k] = cmul(r[k], wk); wk = cmul(wk, w); }
    #pragma unroll
    for (int k = 0; k < 8; k++) sh[k*PADF + tl] = r[k];
    __syncthreads();
    int k0 = tl >> 3, m0 = tl & 7;
    #pragma unroll
    for (int m1 = 0; m1 < 8; m1++) r[m1] = sh[k0*PADF + m0 + 8*m1];
    fft8(r);
    __sincosf(-6.283185307179586f * (float)m0 / 64.0f, &s, &c);
    w = make_float2(c, s); wk = w;
    #pragma unroll
    for (int k = 1; k < 8; k++) { r[k] = cmul(r[k], wk); wk = cmul(wk, w); }
    __syncthreads();
    #pragma unroll
    for (int k = 0; k < 8; k++) sh[k0*PADF + 9*m0 + k] = r[k];
    __syncthreads();
    int k1 = tl & 7;
    #pragma unroll
    for (int m = 0; m < 8; m++) r[m] = sh[k0*PADF + 9*m + k1];
    fft8(r);
}

// ---------------- bin of one (u=row, v=col) unshifted freq point ----------------
__device__ __forceinline__ int binof(int u, int v) {
    int i = (u + H/2) & (H - 1);
    int j = (v + W/2) & (W - 1);
    float yv = lin512(i);
    float xv = lin512(j);

    float rad = sqrtf(xv*xv + yv*yv) / sqrtf(2.0f);
    float a = atan2f(yv, xv);
    a = fmodf(a, PI_F);
    if (a < 0.0f) a += PI_F;

    const float rstep = (0.9f - 0.08f) / 3.0f;
    float re1 = 1.0f * rstep + 0.08f;
    float re2 = 2.0f * rstep + 0.08f;
    int rb = -1;
    if (rad >= 0.08f && rad < re1) rb = 0;
    else if (rad >= re1 && rad < re2) rb = 1;
    else if (rad >= re2 && rad <= 0.9f) rb = 2;

    const float astep = PI_F / 8.0f;
    int ab = 7;
    #pragma unroll
    for (int k = 0; k < 7; k++) {
        float e0 = (float)k * astep;
        float e1 = (float)(k+1) * astep;
        if (a >= e0 && a < e1) { ab = k; break; }
    }
    return (rb >= 0) ? (rb * 8 + ab) : 255;
}

#define NBINBLK 514   // 2 blocks per kcol (256 rows each)

// ---------------- fused: binpair blocks first, then row-FFT blocks ----------------
// grid (NBINBLK + 2048) x 256 threads
//   bid <  NBINBLK : binpair role, kcol = bid>>1, rows [(bid&1)*256, +256)
//   bid >= NBINBLK : rowfft role, b = bid-NBINBLK, img = b>>6, rg = b&63
__global__ void __launch_bounds__(256, 7) k_rowbin(const float* __restrict__ pred,
                                                   const float* __restrict__ tgt) {
    __shared__ float2 sh4[4][SLOT];
    __shared__ int cnt[NBINS];

    const int bid = blockIdx.x;
    const int tid = threadIdx.x;

    if (bid < NBINBLK) {
        // ---- binpair role ----
        const int kcol = bid >> 1;              // 0..256
        const int k = ((bid & 1) << 8) + tid;   // row 0..511
        if (tid < NBINS) cnt[tid] = 0;
        __syncthreads();

        int b1 = binof(k, kcol);
        bool hasm = (kcol >= 1 && kcol <= 255);
        int b2 = hasm ? binof((512 - k) & 511, 512 - kcol) : 255;

        unsigned char e1 = 31, e2 = 255;
        if (b1 < NBINS && b2 == b1) {
            e1 = (unsigned char)(b1 | 64);
            atomicAdd(&cnt[b1], 2);
        } else {
            if (b1 < NBINS) { e1 = (unsigned char)b1; atomicAdd(&cnt[b1], 1); }
            if (b2 < NBINS) { e2 = (unsigned char)b2; atomicAdd(&cnt[b2], 1); }
        }
        d_binpair[kcol * H + k] = make_uchar2(e1, e2);

        __syncthreads();
        if (tid < NBINS && cnt[tid] > 0) atomicAdd(&d_acc.counts[tid], cnt[tid]);
        return;
    }

    // ---- rowfft role ----
    const int b   = bid - NBINBLK;
    const int f  = tid >> 6;
    const int tl = tid & 63;
    const int img = b >> 6;
    const int rg  = b & 63;       // 8-row group

    const float* base = (img < 16)
        ? pred + (size_t)img * 3 * H * W
        : tgt  + (size_t)(img - 16) * 3 * H * W;

    const int rA = rg * 8 + 2 * f;
    const int rB = rA + 1;
    const float wrA = hann512(rA);
    const float wrB = hann512(rB);

    float2 r[8];
    #pragma unroll
    for (int j = 0; j < 8; j++) {
        int col = tl + 64 * j;
        const float* pA = base + (size_t)rA * W + col;
        const float* pB = base + (size_t)rB * W + col;
        float lA = 0.2989f*pA[0] + 0.587f*pA[H*W] + 0.114f*pA[2*H*W];
        float lB = 0.2989f*pB[0] + 0.587f*pB[H*W] + 0.114f*pB[2*H*W];
        float wc = hann512(col);
        r[j] = make_float2(lA * wrA * wc, lB * wrB * wc);
    }

    fft512(r, sh4[f], tl);

    // store spectrum in padded natural order
    __syncthreads();
    {
        int k0 = tl >> 3, k1 = tl & 7;
        #pragma unroll
        for (int k2 = 0; k2 < 8; k2++)
            sh4[f][natidx(k0 + 8*k1 + 64*k2)] = r[k2];
    }
    __syncthreads();

    // block-wide unpack + coalesced transposed write (8 consecutive rows per k)
    const int j    = tid & 7;    // row within group of 8
    const int kidx = tid >> 3;   // 0..31
    const int fp   = j >> 1;     // source FFT slot
    const int isB  = j & 1;
    const float2* z = sh4[fp];
    __half2* dst = d_scratch + (size_t)img * KCOLS * H + rg * 8 + j;

    #pragma unroll
    for (int q = 0; q < 9; q++) {
        int k = kidx + 32 * q;
        if (k > 256) break;
        int km = (512 - k) & 511;
        float2 a = z[natidx(k)];
        float2 bb = z[natidx(km)];
        float2 o;
        if (!isB) o = make_float2(0.5f*(a.x + bb.x),  0.5f*(a.y - bb.y));
        else      o = make_float2(0.5f*(a.y + bb.y), -0.5f*(a.x - bb.x));
        dst[(size_t)k * H] = __floats2half2_rn(o.x, o.y);
    }
}

// ---------------- column pass: FFT + log-magnitude + run-length binning ----
// grid (65, 32), block 256: 4 FFT slots, kcol = bx*4 + f (valid <= 256)
__global__ void __launch_bounds__(256, 8) k_colfft() {
    __shared__ float2 sh4[4][SLOT];
    __shared__ float s_bins[8][NBINS];

    const int tid = threadIdx.x;
    const int f  = tid >> 6;
    const int tl = tid & 63;
    const int img  = blockIdx.y;
    const int kcol = blockIdx.x * 4 + f;
    const int kload = (kcol <= 256) ? kcol : 256;

    for (int i = tid; i < 8 * NBINS; i += 256) ((float*)s_bins)[i] = 0.0f;

    const __half2* src = d_scratch + (size_t)img * KCOLS * H + (size_t)kload * H;
    float2 r[8];
    #pragma unroll
    for (int j = 0; j < 8; j++) r[j] = __half22float2(src[tl + 64 * j]);

    fft512(r, sh4[f], tl);

    // padded natural-order rewrite so each thread owns 8 consecutive rows
    __syncthreads();
    {
        int k0 = tl >> 3, k1 = tl & 7;
        #pragma unroll
        for (int k2 = 0; k2 < 8; k2++)
            sh4[f][natidx(k0 + 8*k1 + 64*k2)] = r[k2];
    }
    __syncthreads();

    if (kcol <= 256) {
        const int warp = tid >> 5;
        const float2* z = sh4[f] + 9 * tl;
        // 8 consecutive uchar2 bin-pairs = one 16B load
        uint4 pv = ((const uint4*)d_binpair)[kcol * 64 + tl];
        unsigned pw[4] = {pv.x, pv.y, pv.z, pv.w};

        int curb = 31;        // current run bin-code (31 = none)
        float acc = 0.0f;
        #pragma unroll
        for (int j = 0; j < 8; j++) {
            float2 fv = z[j];
            float mag = __logf(1.0f + __fsqrt_rn(fv.x*fv.x + fv.y*fv.y));
            unsigned half = pw[j >> 1] >> ((j & 1) * 16);
            unsigned e1 = half & 0xFFu;
            unsigned e2 = (half >> 8) & 0xFFu;
            unsigned b1 = e1 & 31u;
            float wm = (e1 & 64u) ? (mag + mag) : mag;
            if ((int)b1 != curb) {
                if (curb < NBINS) atomicAdd(&s_bins[warp][curb], acc);
                curb = (int)b1; acc = wm;
            } else {
                acc += wm;
            }
            if (e2 < NBINS) atomicAdd(&s_bins[warp][e2], mag);
        }
        if (curb < NBINS) atomicAdd(&s_bins[warp][curb], acc);
    }
    __syncthreads();
    if (tid < NBINS) {
        float s = 0.0f;
        #pragma unroll
        for (int w = 0; w < 8; w++) s += s_bins[w][tid];
        atomicAdd(&d_acc.sums[img * NBINS + tid], s);
    }
}

// ---------------- finalize (slim: 256 threads, 4 barriers, shuffle reduce) ----
__global__ void k_final(const float* __restrict__ rw, float* __restrict__ out) {
    const int tid = threadIdx.x;  // 0..255
    __shared__ float s_e[NIMG * NBINS];   // 768
    __shared__ float s_den[NIMG * 3];     // 96
    __shared__ float s_cnt[NBINS];
    __shared__ float s_w[8];

    if (tid < NBINS)
        s_cnt[tid] = fmaxf((float)d_acc.counts[tid], 1e-6f);
    __syncthreads();
    #pragma unroll
    for (int i = tid; i < NIMG * NBINS; i += 256)
        s_e[i] = d_acc.sums[i] / s_cnt[i % NBINS];
    __syncthreads();
    if (tid < NIMG * 3) {
        int im = tid / 3, rr = tid % 3;
        float s = 0.0f;
        #pragma unroll
        for (int a = 0; a < 8; a++) s += s_e[im * NBINS + rr * 8 + a];
        s_den[tid] = fmaxf(s, 1e-6f);
    }
    __syncthreads();

    float p = 0.0f;
    #pragma unroll
    for (int t = tid; t < 16 * NBINS; t += 256) {
        int b = t / NBINS, rest = t % NBINS, rr = rest / 8;
        float pe = s_e[b * NBINS + rest]        / s_den[b * 3 + rr];
        float te = s_e[(16 + b) * NBINS + rest] / s_den[(16 + b) * 3 + rr];
        float d = pe - te;
        p += sqrtf(d * d + 1e-6f) * rw[rr];
    }
    // warp-shuffle reduction
    #pragma unroll
    for (int off = 16; off > 0; off >>= 1)
        p += __shfl_down_sync(0xFFFFFFFFu, p, off);
    if ((tid & 31) == 0) s_w[tid >> 5] = p;
    __syncthreads();
    if (tid == 0) {
        float s = 0.0f;
        #pragma unroll
        for (int w = 0; w < 8; w++) s += s_w[w];
        out[0] = s / 384.0f;
    }
}

// ---------------- launcher ----------------
extern "C" void kernel_launch(void* const* d_in, const int* in_sizes, int n_in,
                              void* d_out, int out_size) {
    const float* pred = (const float*)d_in[0];
    const float* tgt  = (const float*)d_in[1];
    const float* rw   = (const float*)d_in[2];
    float* out = (float*)d_out;

    // zero accumulators in one memset node (graph-capturable)
    void* p_acc = nullptr;
    cudaGetSymbolAddress(&p_acc, d_acc);
    cudaMemsetAsync(p_acc, 0, sizeof(Acc), 0);

    k_rowbin<<<NBINBLK + 2048, 256>>>(pred, tgt);
    k_colfft<<<dim3(65, NIMG), 256>>>();
    k_final<<<1, 256>>>(rw, out);
}

// round 11
// speedup vs baseline: 1.0817x; 1.0817x over previous
#include <cuda_runtime.h>
#include <cuda_fp16.h>
#include <math.h>

#define PI_F 3.14159274101257324f   // float32(pi)
#define H 512
#define W 512
#define NIMG 32                      // 16 pred + 16 tgt
#define NBINS 24                     // 3 radial * 8 angle
#define KCOLS 257                    // Hermitian: only cols 0..256 stored

// ---- scratch (static device globals; no allocations allowed) ----
__device__ __half2 d_scratch[(size_t)NIMG * KCOLS * H];  // [img][kcol][row], 16.8 MB
struct Acc {
    float sums[NIMG * NBINS];
    int   counts[NBINS];
};
__device__ Acc d_acc;
__device__ __align__(16) uchar2 d_binpair[KCOLS * H];    // per (kcol,row): encoded bin + mirror bin

// float32 linspace(-1, 1, 512) as numpy/jax computes it: i*step + start
__device__ __forceinline__ float lin512(int i) {
    const float step = 2.0f / 511.0f;
    return (float)i * step + (-1.0f);
}
// fast hann window (MUFU cos; abs err ~5e-7, multiplied into input -> negligible)
__device__ __forceinline__ float hann512(int n) {
    return 0.5f * (1.0f - __cosf((6.283185307179586f * (float)n) / 511.0f));
}

// ---------------- packed f32x2 helpers ----------------
__device__ __forceinline__ float2 f2add(float2 a, float2 b) {
    unsigned long long au = *(unsigned long long*)&a;
    unsigned long long bu = *(unsigned long long*)&b;
    unsigned long long ru;
    asm("add.rn.f32x2 %0, %1, %2;" : "=l"(ru) : "l"(au), "l"(bu));
    return *(float2*)&ru;
}
__device__ __forceinline__ float2 f2sub(float2 a, float2 b) {
    unsigned long long au = *(unsigned long long*)&a;
    unsigned long long bu = *(unsigned long long*)&b;
    const float2 n1 = make_float2(-1.0f, -1.0f);
    unsigned long long nu = *(unsigned long long*)&n1;
    unsigned long long ru;
    asm("fma.rn.f32x2 %0, %1, %2, %3;" : "=l"(ru) : "l"(bu), "l"(nu), "l"(au));
    return *(float2*)&ru;
}
__device__ __forceinline__ float2 f2mul(float2 a, float2 b) {
    unsigned long long au = *(unsigned long long*)&a;
    unsigned long long bu = *(unsigned long long*)&b;
    unsigned long long ru;
    asm("mul.rn.f32x2 %0, %1, %2;" : "=l"(ru) : "l"(au), "l"(bu));
    return *(float2*)&ru;
}

// ---------------- complex helpers ----------------
__device__ __forceinline__ float2 cmul(float2 a, float2 b){return make_float2(a.x*b.x-a.y*b.y, a.x*b.y+a.y*b.x);}
__device__ __forceinline__ float2 mulmj(float2 a){return make_float2(a.y,-a.x);} // * (-i)

// 8-point DFT in registers (DIF, natural frequency order out)
__device__ __forceinline__ void fft8(float2 r[8]) {
    const float Cc = 0.70710678118654752f;
    const float2 C2 = make_float2(Cc, Cc);
    float2 u0=f2add(r[0],r[4]), u4=f2sub(r[0],r[4]);
    float2 u1=f2add(r[1],r[5]), u5=f2sub(r[1],r[5]);
    float2 u2=f2add(r[2],r[6]), u6=f2sub(r[2],r[6]);
    float2 u3=f2add(r[3],r[7]), u7=f2sub(r[3],r[7]);
    float2 t5 = f2add(u5, mulmj(u5));      // (x+y, y-x)
    u5 = f2mul(t5, C2);                    // * W8^1
    u6 = mulmj(u6);                        // * W8^2
    float2 t7 = f2add(u7, mulmj(u7));
    u7 = f2mul(mulmj(t7), C2);             // * W8^3
    float2 v0=f2add(u0,u2), v2=f2sub(u0,u2);
    float2 v1=f2add(u1,u3), v3=mulmj(f2sub(u1,u3));
    float2 v4=f2add(u4,u6), v6=f2sub(u4,u6);
    float2 v5=f2add(u5,u7), v7=mulmj(f2sub(u5,u7));
    r[0]=f2add(v0,v1); r[4]=f2sub(v0,v1);
    r[2]=f2add(v2,v3); r[6]=f2sub(v2,v3);
    r[1]=f2add(v4,v5); r[5]=f2sub(v4,v5);
    r[3]=f2add(v6,v7); r[7]=f2sub(v6,v7);
}

#define PADF 72    // float2 stride: 72 mod 16 == 8 -> conflict-free LDS.64/STS.64 both exchanges
#define SLOT 576   // float2 per slot (max idx 574)

// natural-order padded index (conflict-free for consecutive-row reads)
__device__ __forceinline__ int natidx(int k){ return 9*(k>>3) + (k&7); }

// 512-pt FFT: 64 threads (tl), 8 values/thread. Input r[j] = x[tl + 64*j].
// Output: r[k2] = X[k0 + 8*k1 + 64*k2] with k0 = tl>>3, k1 = tl&7.
__device__ __forceinline__ void fft512(float2 r[8], float2* sh, int tl) {
    fft8(r);
    float s, c;
    __sincosf(-6.283185307179586f * (float)tl / 512.0f, &s, &c);
    float2 w = make_float2(c, s), wk = w;
    #pragma unroll
    for (int k = 1; k < 8; k++) { r[k] = cmul(r[k], wk); wk = cmul(wk, w); }
    #pragma unroll
    for (int k = 0; k < 8; k++) sh[k*PADF + tl] = r[k];
    __syncthreads();
    int k0 = tl >> 3, m0 = tl & 7;
    #pragma unroll
    for (int m1 = 0; m1 < 8; m1++) r[m1] = sh[k0*PADF + m0 + 8*m1];
    fft8(r);
    __sincosf(-6.283185307179586f * (float)m0 / 64.0f, &s, &c);
    w = make_float2(c, s); wk = w;
    #pragma unroll
    for (int k = 1; k < 8; k++) { r[k] = cmul(r[k], wk); wk = cmul(wk, w); }
    __syncthreads();
    #pragma unroll
    for (int k = 0; k < 8; k++) sh[k0*PADF + 9*m0 + k] = r[k];
    __syncthreads();
    int k1 = tl & 7;
    #pragma unroll
    for (int m = 0; m < 8; m++) r[m] = sh[k0*PADF + 9*m + k1];
    fft8(r);
}

// ---------------- bin of one (u=row, v=col) unshifted freq point ----------------
__device__ __forceinline__ int binof(int u, int v) {
    int i = (u + H/2) & (H - 1);
    int j = (v + W/2) & (W - 1);
    float yv = lin512(i);
    float xv = lin512(j);

    float rad = sqrtf(xv*xv + yv*yv) / sqrtf(2.0f);
    float a = atan2f(yv, xv);
    a = fmodf(a, PI_F);
    if (a < 0.0f) a += PI_F;

    const float rstep = (0.9f - 0.08f) / 3.0f;
    float re1 = 1.0f * rstep + 0.08f;
    float re2 = 2.0f * rstep + 0.08f;
    int rb = -1;
    if (rad >= 0.08f && rad < re1) rb = 0;
    else if (rad >= re1 && rad < re2) rb = 1;
    else if (rad >= re2 && rad <= 0.9f) rb = 2;

    const float astep = PI_F / 8.0f;
    int ab = 7;
    #pragma unroll
    for (int k = 0; k < 7; k++) {
        float e0 = (float)k * astep;
        float e1 = (float)(k+1) * astep;
        if (a >= e0 && a < e1) { ab = k; break; }
    }
    return (rb >= 0) ? (rb * 8 + ab) : 255;
}

#define NBINBLK 514   // 2 blocks per kcol (256 rows each)

// ---------------- fused: binpair blocks first, then row-FFT blocks ----------------
// grid (NBINBLK + 2048) x 256 threads
//   bid <  NBINBLK : binpair role, kcol = bid>>1, rows [(bid&1)*256, +256)
//   bid >= NBINBLK : rowfft role, b = bid-NBINBLK, img = b>>6, rg = b&63
__global__ void __launch_bounds__(256) k_rowbin(const float* __restrict__ pred,
                                                const float* __restrict__ tgt) {
    __shared__ float2 sh4[4][SLOT];
    __shared__ int cnt[NBINS];

    const int bid = blockIdx.x;
    const int tid = threadIdx.x;

    if (bid < NBINBLK) {
        // ---- binpair role ----
        const int kcol = bid >> 1;              // 0..256
        const int k = ((bid & 1) << 8) + tid;   // row 0..511
        if (tid < NBINS) cnt[tid] = 0;
        __syncthreads();

        int b1 = binof(k, kcol);
        bool hasm = (kcol >= 1 && kcol <= 255);
        int b2 = hasm ? binof((512 - k) & 511, 512 - kcol) : 255;

        unsigned char e1 = 31, e2 = 255;
        if (b1 < NBINS && b2 == b1) {
            e1 = (unsigned char)(b1 | 64);
            atomicAdd(&cnt[b1], 2);
        } else {
            if (b1 < NBINS) { e1 = (unsigned char)b1; atomicAdd(&cnt[b1], 1); }
            if (b2 < NBINS) { e2 = (unsigned char)b2; atomicAdd(&cnt[b2], 1); }
        }
        d_binpair[kcol * H + k] = make_uchar2(e1, e2);

        __syncthreads();
        if (tid < NBINS && cnt[tid] > 0) atomicAdd(&d_acc.counts[tid], cnt[tid]);
        return;
    }

    // ---- rowfft role ----
    const int b   = bid - NBINBLK;
    const int f  = tid >> 6;
    const int tl = tid & 63;
    const int img = b >> 6;
    const int rg  = b & 63;       // 8-row group

    const float* base = (img < 16)
        ? pred + (size_t)img * 3 * H * W
        : tgt  + (size_t)(img - 16) * 3 * H * W;

    const int rA = rg * 8 + 2 * f;
    const int rB = rA + 1;
    const float wrA = hann512(rA);
    const float wrB = hann512(rB);

    float2 r[8];
    #pragma unroll
    for (int j = 0; j < 8; j++) {
        int col = tl + 64 * j;
        const float* pA = base + (size_t)rA * W + col;
        const float* pB = base + (size_t)rB * W + col;
        // streaming (evict-first) reads: input is touched exactly once,
        // keep L2 free for d_scratch which colfft reads next
        float a0 = __ldcs(pA);
        float a1 = __ldcs(pA + H * W);
        float a2 = __ldcs(pA + 2 * H * W);
        float b0 = __ldcs(pB);
        float b1 = __ldcs(pB + H * W);
        float b2 = __ldcs(pB + 2 * H * W);
        float lA = 0.2989f*a0 + 0.587f*a1 + 0.114f*a2;
        float lB = 0.2989f*b0 + 0.587f*b1 + 0.114f*b2;
        float wc = hann512(col);
        r[j] = make_float2(lA * wrA * wc, lB * wrB * wc);
    }

    fft512(r, sh4[f], tl);

    // store spectrum in padded natural order
    __syncthreads();
    {
        int k0 = tl >> 3, k1 = tl & 7;
        #pragma unroll
        for (int k2 = 0; k2 < 8; k2++)
            sh4[f][natidx(k0 + 8*k1 + 64*k2)] = r[k2];
    }
    __syncthreads();

    // block-wide unpack + coalesced transposed write (8 consecutive rows per k)
    const int j    = tid & 7;    // row within group of 8
    const int kidx = tid >> 3;   // 0..31
    const int fp   = j >> 1;     // source FFT slot
    const int isB  = j & 1;
    const float2* z = sh4[fp];
    __half2* dst = d_scratch + (size_t)img * KCOLS * H + rg * 8 + j;

    #pragma unroll
    for (int q = 0; q < 9; q++) {
        int k = kidx + 32 * q;
        if (k > 256) break;
        int km = (512 - k) & 511;
        float2 a = z[natidx(k)];
        float2 bb = z[natidx(km)];
        float2 o;
        if (!isB) o = make_float2(0.5f*(a.x + bb.x),  0.5f*(a.y - bb.y));
        else      o = make_float2(0.5f*(a.y + bb.y), -0.5f*(a.x - bb.x));
        dst[(size_t)k * H] = __floats2half2_rn(o.x, o.y);
    }
}

// ---------------- column pass: FFT + log-magnitude + run-length binning ----
// grid (65, 32), block 256: 4 FFT slots, kcol = bx*4 + f (valid <= 256)
__global__ void __launch_bounds__(256, 8) k_colfft() {
    __shared__ float2 sh4[4][SLOT];
    __shared__ float s_bins[8][NBINS];

    const int tid = threadIdx.x;
    const int f  = tid >> 6;
    const int tl = tid & 63;
    const int img  = blockIdx.y;
    const int kcol = blockIdx.x * 4 + f;
    const int kload = (kcol <= 256) ? kcol : 256;

    for (int i = tid; i < 8 * NBINS; i += 256) ((float*)s_bins)[i] = 0.0f;

    const __half2* src = d_scratch + (size_t)img * KCOLS * H + (size_t)kload * H;
    float2 r[8];
    #pragma unroll
    for (int j = 0; j < 8; j++) r[j] = __half22float2(src[tl + 64 * j]);

    fft512(r, sh4[f], tl);

    // padded natural-order rewrite so each thread owns 8 consecutive rows
    __syncthreads();
    {
        int k0 = tl >> 3, k1 = tl & 7;
        #pragma unroll
        for (int k2 = 0; k2 < 8; k2++)
            sh4[f][natidx(k0 + 8*k1 + 64*k2)] = r[k2];
    }
    __syncthreads();

    if (kcol <= 256) {
        const int warp = tid >> 5;
        const float2* z = sh4[f] + 9 * tl;
        // 8 consecutive uchar2 bin-pairs = one 16B load
        uint4 pv = ((const uint4*)d_binpair)[kcol * 64 + tl];
        unsigned pw[4] = {pv.x, pv.y, pv.z, pv.w};

        int curb = 31;        // current run bin-code (31 = none)
        float acc = 0.0f;
        #pragma unroll
        for (int j = 0; j < 8; j++) {
            float2 fv = z[j];
            float mag = __logf(1.0f + __fsqrt_rn(fv.x*fv.x + fv.y*fv.y));
            unsigned half = pw[j >> 1] >> ((j & 1) * 16);
            unsigned e1 = half & 0xFFu;
            unsigned e2 = (half >> 8) & 0xFFu;
            unsigned b1 = e1 & 31u;
            float wm = (e1 & 64u) ? (mag + mag) : mag;
            if ((int)b1 != curb) {
                if (curb < NBINS) atomicAdd(&s_bins[warp][curb], acc);
                curb = (int)b1; acc = wm;
            } else {
                acc += wm;
            }
            if (e2 < NBINS) atomicAdd(&s_bins[warp][e2], mag);
        }
        if (curb < NBINS) atomicAdd(&s_bins[warp][curb], acc);
    }
    __syncthreads();
    if (tid < NBINS) {
        float s = 0.0f;
        #pragma unroll
        for (int w = 0; w < 8; w++) s += s_bins[w][tid];
        atomicAdd(&d_acc.sums[img * NBINS + tid], s);
    }
}

// ---------------- finalize (slim: 256 threads, 4 barriers, shuffle reduce) ----
__global__ void k_final(const float* __restrict__ rw, float* __restrict__ out) {
    const int tid = threadIdx.x;  // 0..255
    __shared__ float s_e[NIMG * NBINS];   // 768
    __shared__ float s_den[NIMG * 3];     // 96
    __shared__ float s_cnt[NBINS];
    __shared__ float s_w[8];

    if (tid < NBINS)
        s_cnt[tid] = fmaxf((float)d_acc.counts[tid], 1e-6f);
    __syncthreads();
    #pragma unroll
    for (int i = tid; i < NIMG * NBINS; i += 256)
        s_e[i] = d_acc.sums[i] / s_cnt[i % NBINS];
    __syncthreads();
    if (tid < NIMG * 3) {
        int im = tid / 3, rr = tid % 3;
        float s = 0.0f;
        #pragma unroll
        for (int a = 0; a < 8; a++) s += s_e[im * NBINS + rr * 8 + a];
        s_den[tid] = fmaxf(s, 1e-6f);
    }
    __syncthreads();

    float p = 0.0f;
    #pragma unroll
    for (int t = tid; t < 16 * NBINS; t += 256) {
        int b = t / NBINS, rest = t % NBINS, rr = rest / 8;
        float pe = s_e[b * NBINS + rest]        / s_den[b * 3 + rr];
        float te = s_e[(16 + b) * NBINS + rest] / s_den[(16 + b) * 3 + rr];
        float d = pe - te;
        p += sqrtf(d * d + 1e-6f) * rw[rr];
    }
    // warp-shuffle reduction
    #pragma unroll
    for (int off = 16; off > 0; off >>= 1)
        p += __shfl_down_sync(0xFFFFFFFFu, p, off);
    if ((tid & 31) == 0) s_w[tid >> 5] = p;
    __syncthreads();
    if (tid == 0) {
        float s = 0.0f;
        #pragma unroll
        for (int w = 0; w < 8; w++) s += s_w[w];
        out[0] = s / 384.0f;
    }
}

// ---------------- launcher ----------------
extern "C" void kernel_launch(void* const* d_in, const int* in_sizes, int n_in,
                              void* d_out, int out_size) {
    const float* pred = (const float*)d_in[0];
    const float* tgt  = (const float*)d_in[1];
    const float* rw   = (const float*)d_in[2];
    float* out = (float*)d_out;

    // zero accumulators in one memset node (graph-capturable)
    void* p_acc = nullptr;
    cudaGetSymbolAddress(&p_acc, d_acc);
    cudaMemsetAsync(p_acc, 0, sizeof(Acc), 0);

    k_rowbin<<<NBINBLK + 2048, 256>>>(pred, tgt);
    k_colfft<<<dim3(65, NIMG), 256>>>();
    k_final<<<1, 256>>>(rw, out);
}

// round 12
// speedup vs baseline: 1.2674x; 1.1717x over previous
#include <cuda_runtime.h>
#include <cuda_fp16.h>
#include <math.h>

#define PI_F 3.14159274101257324f   // float32(pi)
#define H 512
#define W 512
#define NIMG 32                      // 16 pred + 16 tgt
#define NBINS 24                     // 3 radial * 8 angle
#define KCOLS 257                    // Hermitian: only cols 0..256 stored

// ---- scratch (static device globals; no allocations allowed) ----
__device__ __half2 d_scratch[(size_t)NIMG * KCOLS * H];  // [img][kcol][row], 16.8 MB
struct Acc {
    float sums[NIMG * NBINS];
    int   counts[NBINS];
};
__device__ Acc d_acc;
__device__ __align__(16) uchar2 d_binpair[KCOLS * H];    // per (kcol,row): encoded bin + mirror bin

// float32 linspace(-1, 1, 512) as numpy/jax computes it: i*step + start
__device__ __forceinline__ float lin512(int i) {
    const float step = 2.0f / 511.0f;
    return (float)i * step + (-1.0f);
}
// fast hann window (MUFU cos; abs err ~5e-7, multiplied into input -> negligible)
__device__ __forceinline__ float hann512(int n) {
    return 0.5f * (1.0f - __cosf((6.283185307179586f * (float)n) / 511.0f));
}

// ---------------- packed f32x2 helpers ----------------
__device__ __forceinline__ float2 f2add(float2 a, float2 b) {
    unsigned long long au = *(unsigned long long*)&a;
    unsigned long long bu = *(unsigned long long*)&b;
    unsigned long long ru;
    asm("add.rn.f32x2 %0, %1, %2;" : "=l"(ru) : "l"(au), "l"(bu));
    return *(float2*)&ru;
}
__device__ __forceinline__ float2 f2sub(float2 a, float2 b) {
    unsigned long long au = *(unsigned long long*)&a;
    unsigned long long bu = *(unsigned long long*)&b;
    const float2 n1 = make_float2(-1.0f, -1.0f);
    unsigned long long nu = *(unsigned long long*)&n1;
    unsigned long long ru;
    asm("fma.rn.f32x2 %0, %1, %2, %3;" : "=l"(ru) : "l"(bu), "l"(nu), "l"(au));
    return *(float2*)&ru;
}
__device__ __forceinline__ float2 f2mul(float2 a, float2 b) {
    unsigned long long au = *(unsigned long long*)&a;
    unsigned long long bu = *(unsigned long long*)&b;
    unsigned long long ru;
    asm("mul.rn.f32x2 %0, %1, %2;" : "=l"(ru) : "l"(au), "l"(bu));
    return *(float2*)&ru;
}

// ---------------- complex helpers ----------------
__device__ __forceinline__ float2 cmul(float2 a, float2 b){return make_float2(a.x*b.x-a.y*b.y, a.x*b.y+a.y*b.x);}
__device__ __forceinline__ float2 mulmj(float2 a){return make_float2(a.y,-a.x);} // * (-i)

// 8-point DFT in registers (DIF, natural frequency order out)
__device__ __forceinline__ void fft8(float2 r[8]) {
    const float Cc = 0.70710678118654752f;
    const float2 C2 = make_float2(Cc, Cc);
    float2 u0=f2add(r[0],r[4]), u4=f2sub(r[0],r[4]);
    float2 u1=f2add(r[1],r[5]), u5=f2sub(r[1],r[5]);
    float2 u2=f2add(r[2],r[6]), u6=f2sub(r[2],r[6]);
    float2 u3=f2add(r[3],r[7]), u7=f2sub(r[3],r[7]);
    float2 t5 = f2add(u5, mulmj(u5));      // (x+y, y-x)
    u5 = f2mul(t5, C2);                    // * W8^1
    u6 = mulmj(u6);                        // * W8^2
    float2 t7 = f2add(u7, mulmj(u7));
    u7 = f2mul(mulmj(t7), C2);             // * W8^3
    float2 v0=f2add(u0,u2), v2=f2sub(u0,u2);
    float2 v1=f2add(u1,u3), v3=mulmj(f2sub(u1,u3));
    float2 v4=f2add(u4,u6), v6=f2sub(u4,u6);
    float2 v5=f2add(u5,u7), v7=mulmj(f2sub(u5,u7));
    r[0]=f2add(v0,v1); r[4]=f2sub(v0,v1);
    r[2]=f2add(v2,v3); r[6]=f2sub(v2,v3);
    r[1]=f2add(v4,v5); r[5]=f2sub(v4,v5);
    r[3]=f2add(v6,v7); r[7]=f2sub(v6,v7);
}

#define PADF 72    // float2 stride: 72 mod 16 == 8 -> conflict-free LDS.64/STS.64 both exchanges
#define SLOT 576   // float2 per slot (max idx 574)

// natural-order padded index (conflict-free for consecutive-row reads)
__device__ __forceinline__ int natidx(int k){ return 9*(k>>3) + (k&7); }
// staging index for luma: conflict-free for 4-consecutive writes and 64-strided reads
__device__ __forceinline__ int stgidx(int c){ return c + (c >> 4); }

// 512-pt FFT: 64 threads (tl), 8 values/thread. Input r[j] = x[tl + 64*j].
// Output: r[k2] = X[k0 + 8*k1 + 64*k2] with k0 = tl>>3, k1 = tl&7.
__device__ __forceinline__ void fft512(float2 r[8], float2* sh, int tl) {
    fft8(r);
    float s, c;
    __sincosf(-6.283185307179586f * (float)tl / 512.0f, &s, &c);
    float2 w = make_float2(c, s), wk = w;
    #pragma unroll
    for (int k = 1; k < 8; k++) { r[k] = cmul(r[k], wk); wk = cmul(wk, w); }
    #pragma unroll
    for (int k = 0; k < 8; k++) sh[k*PADF + tl] = r[k];
    __syncthreads();
    int k0 = tl >> 3, m0 = tl & 7;
    #pragma unroll
    for (int m1 = 0; m1 < 8; m1++) r[m1] = sh[k0*PADF + m0 + 8*m1];
    fft8(r);
    __sincosf(-6.283185307179586f * (float)m0 / 64.0f, &s, &c);
    w = make_float2(c, s); wk = w;
    #pragma unroll
    for (int k = 1; k < 8; k++) { r[k] = cmul(r[k], wk); wk = cmul(wk, w); }
    __syncthreads();
    #pragma unroll
    for (int k = 0; k < 8; k++) sh[k0*PADF + 9*m0 + k] = r[k];
    __syncthreads();
    int k1 = tl & 7;
    #pragma unroll
    for (int m = 0; m < 8; m++) r[m] = sh[k0*PADF + 9*m + k1];
    fft8(r);
}

// ---------------- bin of one (u=row, v=col) unshifted freq point ----------------
__device__ __forceinline__ int binof(int u, int v) {
    int i = (u + H/2) & (H - 1);
    int j = (v + W/2) & (W - 1);
    float yv = lin512(i);
    float xv = lin512(j);

    float rad = sqrtf(xv*xv + yv*yv) / sqrtf(2.0f);
    float a = atan2f(yv, xv);
    a = fmodf(a, PI_F);
    if (a < 0.0f) a += PI_F;

    const float rstep = (0.9f - 0.08f) / 3.0f;
    float re1 = 1.0f * rstep + 0.08f;
    float re2 = 2.0f * rstep + 0.08f;
    int rb = -1;
    if (rad >= 0.08f && rad < re1) rb = 0;
    else if (rad >= re1 && rad < re2) rb = 1;
    else if (rad >= re2 && rad <= 0.9f) rb = 2;

    const float astep = PI_F / 8.0f;
    int ab = 7;
    #pragma unroll
    for (int k = 0; k < 7; k++) {
        float e0 = (float)k * astep;
        float e1 = (float)(k+1) * astep;
        if (a >= e0 && a < e1) { ab = k; break; }
    }
    return (rb >= 0) ? (rb * 8 + ab) : 255;
}

#define NBINBLK 514   // 2 blocks per kcol (256 rows each)

// ---------------- fused: binpair blocks first, then row-FFT blocks ----------------
// grid (NBINBLK + 2048) x 256 threads
//   bid <  NBINBLK : binpair role, kcol = bid>>1, rows [(bid&1)*256, +256)
//   bid >= NBINBLK : rowfft role, b = bid-NBINBLK, img = b>>6, rg = b&63
__global__ void __launch_bounds__(256) k_rowbin(const float* __restrict__ pred,
                                                const float* __restrict__ tgt) {
    __shared__ float2 sh4[4][SLOT];
    __shared__ int cnt[NBINS];

    const int bid = blockIdx.x;
    const int tid = threadIdx.x;

    if (bid < NBINBLK) {
        // ---- binpair role ----
        const int kcol = bid >> 1;              // 0..256
        const int k = ((bid & 1) << 8) + tid;   // row 0..511
        if (tid < NBINS) cnt[tid] = 0;
        __syncthreads();

        int b1 = binof(k, kcol);
        bool hasm = (kcol >= 1 && kcol <= 255);
        int b2 = hasm ? binof((512 - k) & 511, 512 - kcol) : 255;

        unsigned char e1 = 31, e2 = 255;
        if (b1 < NBINS && b2 == b1) {
            e1 = (unsigned char)(b1 | 64);
            atomicAdd(&cnt[b1], 2);
        } else {
            if (b1 < NBINS) { e1 = (unsigned char)b1; atomicAdd(&cnt[b1], 1); }
            if (b2 < NBINS) { e2 = (unsigned char)b2; atomicAdd(&cnt[b2], 1); }
        }
        d_binpair[kcol * H + k] = make_uchar2(e1, e2);

        __syncthreads();
        if (tid < NBINS && cnt[tid] > 0) atomicAdd(&d_acc.counts[tid], cnt[tid]);
        return;
    }

    // ---- rowfft role ----
    const int b   = bid - NBINBLK;
    const int f  = tid >> 6;
    const int tl = tid & 63;
    const int img = b >> 6;
    const int rg  = b & 63;       // 8-row group

    const float* base = (img < 16)
        ? pred + (size_t)img * 3 * H * W
        : tgt  + (size_t)(img - 16) * 3 * H * W;

    const int rA = rg * 8 + 2 * f;
    const int rB = rA + 1;
    const float wrA = hann512(rA);
    const float wrB = hann512(rB);

    // vectorized input: float4 loads, luma+window, stage to shared
    {
        const int HW4 = H * W / 4;
        const float4* pA = (const float4*)(base + (size_t)rA * W);
        const float4* pB = (const float4*)(base + (size_t)rB * W);
        float2* stg = sh4[f];
        #pragma unroll
        for (int g = 0; g < 2; g++) {
            int c4 = tl + 64 * g;          // float4 index; col = 4*c4
            float4 a0 = __ldcs(pA + c4);
            float4 a1 = __ldcs(pA + HW4 + c4);
            float4 a2 = __ldcs(pA + 2 * HW4 + c4);
            float4 b0 = __ldcs(pB + c4);
            float4 b1 = __ldcs(pB + HW4 + c4);
            float4 b2 = __ldcs(pB + 2 * HW4 + c4);
            float ra0[4] = {a0.x, a0.y, a0.z, a0.w};
            float ra1[4] = {a1.x, a1.y, a1.z, a1.w};
            float ra2[4] = {a2.x, a2.y, a2.z, a2.w};
            float rb0[4] = {b0.x, b0.y, b0.z, b0.w};
            float rb1[4] = {b1.x, b1.y, b1.z, b1.w};
            float rb2[4] = {b2.x, b2.y, b2.z, b2.w};
            #pragma unroll
            for (int i = 0; i < 4; i++) {
                int col = 4 * c4 + i;
                float lA = 0.2989f*ra0[i] + 0.587f*ra1[i] + 0.114f*ra2[i];
                float lB = 0.2989f*rb0[i] + 0.587f*rb1[i] + 0.114f*rb2[i];
                float wc = hann512(col);
                stg[stgidx(col)] = make_float2(lA * wrA * wc, lB * wrB * wc);
            }
        }
    }
    __syncthreads();

    float2 r[8];
    #pragma unroll
    for (int j = 0; j < 8; j++) r[j] = sh4[f][stgidx(tl + 64 * j)];
    __syncthreads();   // staging reads complete before fft512 overwrites sh4

    fft512(r, sh4[f], tl);

    // store spectrum in padded natural order
    __syncthreads();
    {
        int k0 = tl >> 3, k1 = tl & 7;
        #pragma unroll
        for (int k2 = 0; k2 < 8; k2++)
            sh4[f][natidx(k0 + 8*k1 + 64*k2)] = r[k2];
    }
    __syncthreads();

    // block-wide unpack + coalesced transposed write (8 consecutive rows per k)
    const int j    = tid & 7;    // row within group of 8
    const int kidx = tid >> 3;   // 0..31
    const int fp   = j >> 1;     // source FFT slot
    const int isB  = j & 1;
    const float2* z = sh4[fp];
    __half2* dst = d_scratch + (size_t)img * KCOLS * H + rg * 8 + j;

    #pragma unroll
    for (int q = 0; q < 9; q++) {
        int k = kidx + 32 * q;
        if (k > 256) break;
        int km = (512 - k) & 511;
        float2 a = z[natidx(k)];
        float2 bb = z[natidx(km)];
        float2 o;
        if (!isB) o = make_float2(0.5f*(a.x + bb.x),  0.5f*(a.y - bb.y));
        else      o = make_float2(0.5f*(a.y + bb.y), -0.5f*(a.x - bb.x));
        dst[(size_t)k * H] = __floats2half2_rn(o.x, o.y);
    }
}

// ---------------- column pass: FFT + log-magnitude + run-length binning ----
// grid (65, 32), block 256: 4 FFT slots, kcol = bx*4 + f (valid <= 256)
__global__ void __launch_bounds__(256, 8) k_colfft() {
    __shared__ float2 sh4[4][SLOT];
    __shared__ float s_bins[8][NBINS];

    const int tid = threadIdx.x;
    const int f  = tid >> 6;
    const int tl = tid & 63;
    const int img  = blockIdx.y;
    const int kcol = blockIdx.x * 4 + f;
    const int kload = (kcol <= 256) ? kcol : 256;

    for (int i = tid; i < 8 * NBINS; i += 256) ((float*)s_bins)[i] = 0.0f;

    const __half2* src = d_scratch + (size_t)img * KCOLS * H + (size_t)kload * H;
    float2 r[8];
    #pragma unroll
    for (int j = 0; j < 8; j++) r[j] = __half22float2(src[tl + 64 * j]);

    fft512(r, sh4[f], tl);

    // padded natural-order rewrite so each thread owns 8 consecutive rows
    __syncthreads();
    {
        int k0 = tl >> 3, k1 = tl & 7;
        #pragma unroll
        for (int k2 = 0; k2 < 8; k2++)
            sh4[f][natidx(k0 + 8*k1 + 64*k2)] = r[k2];
    }
    __syncthreads();

    if (kcol <= 256) {
        const int warp = tid >> 5;
        const float2* z = sh4[f] + 9 * tl;
        // 8 consecutive uchar2 bin-pairs = one 16B load
        uint4 pv = ((const uint4*)d_binpair)[kcol * 64 + tl];
        unsigned pw[4] = {pv.x, pv.y, pv.z, pv.w};

        int curb = 31;        // current run bin-code (31 = none)
        float acc = 0.0f;
        #pragma unroll
        for (int j = 0; j < 8; j++) {
            float2 fv = z[j];
            float mag = __logf(1.0f + __fsqrt_rn(fv.x*fv.x + fv.y*fv.y));
            unsigned half = pw[j >> 1] >> ((j & 1) * 16);
            unsigned e1 = half & 0xFFu;
            unsigned e2 = (half >> 8) & 0xFFu;
            unsigned b1 = e1 & 31u;
            float wm = (e1 & 64u) ? (mag + mag) : mag;
            if ((int)b1 != curb) {
                if (curb < NBINS) atomicAdd(&s_bins[warp][curb], acc);
                curb = (int)b1; acc = wm;
            } else {
                acc += wm;
            }
            if (e2 < NBINS) atomicAdd(&s_bins[warp][e2], mag);
        }
        if (curb < NBINS) atomicAdd(&s_bins[warp][curb], acc);
    }
    __syncthreads();
    if (tid < NBINS) {
        float s = 0.0f;
        #pragma unroll
        for (int w = 0; w < 8; w++) s += s_bins[w][tid];
        atomicAdd(&d_acc.sums[img * NBINS + tid], s);
    }
}

// ---------------- finalize (slim: 256 threads, 4 barriers, shuffle reduce) ----
__global__ void k_final(const float* __restrict__ rw, float* __restrict__ out) {
    const int tid = threadIdx.x;  // 0..255
    __shared__ float s_e[NIMG * NBINS];   // 768
    __shared__ float s_den[NIMG * 3];     // 96
    __shared__ float s_cnt[NBINS];
    __shared__ float s_w[8];

    if (tid < NBINS)
        s_cnt[tid] = fmaxf((float)d_acc.counts[tid], 1e-6f);
    __syncthreads();
    #pragma unroll
    for (int i = tid; i < NIMG * NBINS; i += 256)
        s_e[i] = d_acc.sums[i] / s_cnt[i % NBINS];
    __syncthreads();
    if (tid < NIMG * 3) {
        int im = tid / 3, rr = tid % 3;
        float s = 0.0f;
        #pragma unroll
        for (int a = 0; a < 8; a++) s += s_e[im * NBINS + rr * 8 + a];
        s_den[tid] = fmaxf(s, 1e-6f);
    }
    __syncthreads();

    float p = 0.0f;
    #pragma unroll
    for (int t = tid; t < 16 * NBINS; t += 256) {
        int b = t / NBINS, rest = t % NBINS, rr = rest / 8;
        float pe = s_e[b * NBINS + rest]        / s_den[b * 3 + rr];
        float te = s_e[(16 + b) * NBINS + rest] / s_den[(16 + b) * 3 + rr];
        float d = pe - te;
        p += sqrtf(d * d + 1e-6f) * rw[rr];
    }
    // warp-shuffle reduction
    #pragma unroll
    for (int off = 16; off > 0; off >>= 1)
        p += __shfl_down_sync(0xFFFFFFFFu, p, off);
    if ((tid & 31) == 0) s_w[tid >> 5] = p;
    __syncthreads();
    if (tid == 0) {
        float s = 0.0f;
        #pragma unroll
        for (int w = 0; w < 8; w++) s += s_w[w];
        out[0] = s / 384.0f;
    }
}

// ---------------- launcher ----------------
extern "C" void kernel_launch(void* const* d_in, const int* in_sizes, int n_in,
                              void* d_out, int out_size) {
    const float* pred = (const float*)d_in[0];
    const float* tgt  = (const float*)d_in[1];
    const float* rw   = (const float*)d_in[2];
    float* out = (float*)d_out;

    // zero accumulators in one memset node (graph-capturable)
    void* p_acc = nullptr;
    cudaGetSymbolAddress(&p_acc, d_acc);
    cudaMemsetAsync(p_acc, 0, sizeof(Acc), 0);

    k_rowbin<<<NBINBLK + 2048, 256>>>(pred, tgt);
    k_colfft<<<dim3(65, NIMG), 256>>>();
    k_final<<<1, 256>>>(rw, out);
}